// round 12
// baseline (speedup 1.0000x reference)
#include <cuda_runtime.h>
#include <cuda_bf16.h>
#include <math.h>
#include <stdint.h>

#define NN 50000
#define ER 600000
#define HC 128
#define NB 50
#define NTILES ((NN + 127) / 128)   // 391
#define SBLK 256
#define NSB ((NN + SBLK - 1) / SBLK)   // 196

// ---------------- scratch (static device globals; no allocation) -------------
__device__ float    g_x[NN * HC];
__device__ float    g_res[NN * HC];
__device__ float    g_xl[NN * HC];
__device__ float    g_xr[NN * HC];
__device__ int      g_deg[NN];
__device__ int      g_rowptr[NN + 1];
__device__ int      g_cur[NN];
__device__ int      g_scan_rdy[NSB];     // memset to 0 each call; holds prefix+1
__device__ int4     g_cedge[ER];         // {src, 0, ea.x bits, ea.y bits}
__device__ float    g_mean[NB * HC];
__device__ unsigned g_maxenc[NB * HC];
__device__ float    g_cnt[NB];
__device__ float    g_X[NB * 256];
__device__ unsigned g_Bfrag[8 * 2 * 8 * 16 * 32 * 4];   // 1 MB

__device__ __forceinline__ unsigned encf(float f) {
    unsigned u = __float_as_uint(f);
    return (u & 0x80000000u) ? ~u : (u | 0x80000000u);
}
__device__ __forceinline__ float decf(unsigned u) {
    return __uint_as_float((u & 0x80000000u) ? (u & 0x7fffffffu) : ~u);
}
__device__ __forceinline__ unsigned pack_hi2(float x, float y) {
    __nv_bfloat16 hx = __float2bfloat16(x), hy = __float2bfloat16(y);
    return (unsigned)__bfloat16_as_ushort(hx) | ((unsigned)__bfloat16_as_ushort(hy) << 16);
}
__device__ __forceinline__ unsigned pack_lo2(float x, float y) {
    __nv_bfloat16 hx = __float2bfloat16(x), hy = __float2bfloat16(y);
    __nv_bfloat16 lx = __float2bfloat16(x - __bfloat162float(hx));
    __nv_bfloat16 ly = __float2bfloat16(y - __bfloat162float(hy));
    return (unsigned)__bfloat16_as_ushort(lx) | ((unsigned)__bfloat16_as_ushort(ly) << 16);
}

#define MMA16816(d, a0, a1, a2, a3, b0, b1) \
    asm volatile("mma.sync.aligned.m16n8k16.row.col.f32.bf16.bf16.f32 " \
        "{%0,%1,%2,%3}, {%4,%5,%6,%7}, {%8,%9}, {%0,%1,%2,%3};" \
        : "+f"((d)[0]), "+f"((d)[1]), "+f"((d)[2]), "+f"((d)[3]) \
        : "r"(a0), "r"(a1), "r"(a2), "r"(a3), "r"(b0), "r"(b1))

// ---------------- CSR build ----------------------------------------------------
__global__ void csr_hist_kernel(const int* __restrict__ ei) {
    int e = blockIdx.x * blockDim.x + threadIdx.x;
    if (e < ER) atomicAdd(&g_deg[ei[ER + e]], 1);
}

// single-kernel chained scan: block b waits for flag of b-1 (flag = prefix+1)
__global__ void csr_scan_chain_kernel() {
    __shared__ int sh[SBLK];
    __shared__ int prevs;
    int b = blockIdx.x, t = threadIdx.x;
    int i = b * SBLK + t;
    int v = (i < NN) ? g_deg[i] : 0;
    sh[t] = v;
    __syncthreads();
    for (int o = 1; o < SBLK; o <<= 1) {
        int u = (t >= o) ? sh[t - o] : 0;
        __syncthreads();
        sh[t] += u;
        __syncthreads();
    }
    if (t == 0) {
        int prev = 0;
        if (b > 0) {
            int f;
            do { f = atomicAdd(&g_scan_rdy[b - 1], 0); } while (f == 0);
            prev = f - 1;
        }
        prevs = prev;
        atomicExch(&g_scan_rdy[b], prev + sh[SBLK - 1] + 1);
    }
    __syncthreads();
    int excl = prevs + sh[t] - v;
    if (i < NN) {
        g_rowptr[i] = excl;
        g_cur[i] = excl;
        if (i == NN - 1) g_rowptr[NN] = excl + v;
    }
}

// fused: CSR scatter (i < ER) + conv0 dual linear (i < NN*HC)
__global__ void scatter_lin0_kernel(const int* __restrict__ ei, const float* __restrict__ ea,
                                    const float* __restrict__ nodes,
                                    const float* __restrict__ W0l, const float* __restrict__ b0l,
                                    const float* __restrict__ W0r, const float* __restrict__ b0r) {
    int i = blockIdx.x * blockDim.x + threadIdx.x;
    if (i < ER) {
        int s = ei[i], d = ei[ER + i];
        int p = atomicAdd(&g_cur[d], 1);
        int4 rec;
        rec.x = s;
        rec.y = 0;
        rec.z = __float_as_int(ea[2 * i]);
        rec.w = __float_as_int(ea[2 * i + 1]);
        g_cedge[p] = rec;
    }
    if (i < NN * HC) {
        int n = i >> 7, c = i & 127;
        float4 nd = *(const float4*)(nodes + n * 4);
        float l = b0l[c] + nd.x * W0l[c] + nd.y * W0l[128 + c] + nd.z * W0l[256 + c] + nd.w * W0l[384 + c];
        float r = b0r[c] + nd.x * W0r[c] + nd.y * W0r[128 + c] + nd.z * W0r[256 + c] + nd.w * W0r[384 + c];
        g_xl[i] = l;
        g_xr[i] = r;
    }
}

// ---------------- weight prepass: W -> per-lane mma B fragments ----------------
__global__ void wprep_kernel(const float* __restrict__ Wl, const float* __restrict__ Wr) {
    int i = blockIdx.x * blockDim.x + threadIdx.x;
    if (i >= 262144) return;
    int reg = i & 3;
    int lane = (i >> 2) & 31;
    int nt = (i >> 7) & 15;
    int kstep = (i >> 11) & 7;
    int o = (i >> 14) & 1;
    int t = i >> 15;
    const float* W = (o ? Wr : Wl) + t * 16384;
    int n = nt * 8 + (lane >> 2);
    int k = kstep * 16 + (lane & 3) * 2 + ((reg & 1) ? 8 : 0);
    float v0 = W[k * 128 + n];
    float v1 = W[(k + 1) * 128 + n];
    g_Bfrag[i] = (reg < 2) ? pack_hi2(v0, v1) : pack_lo2(v0, v1);
}

// ---------------- mma.sync dual GEMM, B loaded in 32KB n-halves ----------------
#define GSM_ALO 34816
#define GSM_B   69632
#define GSM_TOTAL (69632 + 32768)

__global__ void __launch_bounds__(256, 2) gemm_mma_kernel(
        int layer, const float* __restrict__ bl, const float* __restrict__ br) {
    extern __shared__ __align__(16) char smem[];
    unsigned* Ahi = (unsigned*)smem;
    unsigned* Alo = (unsigned*)(smem + GSM_ALO);
    uint4*    Bs  = (uint4*)(smem + GSM_B);
    int tid = threadIdx.x, wid = tid >> 5, lane = tid & 31;
    int row0 = blockIdx.x * 128;

    for (int j = tid; j < 4096; j += 256) {
        int r = j >> 5, c4 = j & 31;
        int gr = row0 + r;
        float4 v = (gr < NN) ? *(const float4*)(g_x + gr * HC + c4 * 4)
                             : make_float4(0.f, 0.f, 0.f, 0.f);
        int w = r * 68 + c4 * 2;
        Ahi[w]     = pack_hi2(v.x, v.y);
        Ahi[w + 1] = pack_hi2(v.z, v.w);
        Alo[w]     = pack_lo2(v.x, v.y);
        Alo[w + 1] = pack_lo2(v.z, v.w);
    }

    int ab = (wid * 16 + (lane >> 2)) * 68 + (lane & 3);
#pragma unroll
    for (int o = 0; o < 2; o++) {
        const float* bias = o ? br : bl;
        float* dst = o ? g_xr : g_xl;
#pragma unroll
        for (int half = 0; half < 2; half++) {
            __syncthreads();
            {
                const uint4* src = (const uint4*)g_Bfrag + (layer * 2 + o) * 4096;
                for (int j = tid; j < 2048; j += 256) {
                    int chunk = j >> 5;
                    int ks = chunk >> 3, ntl = chunk & 7;
                    Bs[j] = src[(ks * 16 + half * 8 + ntl) * 32 + (j & 31)];
                }
            }
            __syncthreads();

            float d[8][4];
#pragma unroll
            for (int nt = 0; nt < 8; nt++) {
                d[nt][0] = 0.f; d[nt][1] = 0.f; d[nt][2] = 0.f; d[nt][3] = 0.f;
            }
#pragma unroll
            for (int ks = 0; ks < 8; ks++) {
                unsigned ah0 = Ahi[ab + ks * 8];
                unsigned ah1 = Ahi[ab + 8 * 68 + ks * 8];
                unsigned ah2 = Ahi[ab + ks * 8 + 4];
                unsigned ah3 = Ahi[ab + 8 * 68 + ks * 8 + 4];
                unsigned al0 = Alo[ab + ks * 8];
                unsigned al1 = Alo[ab + 8 * 68 + ks * 8];
                unsigned al2 = Alo[ab + ks * 8 + 4];
                unsigned al3 = Alo[ab + 8 * 68 + ks * 8 + 4];
#pragma unroll
                for (int nt = 0; nt < 8; nt++) {
                    uint4 b = Bs[(ks * 8 + nt) * 32 + lane];
                    MMA16816(d[nt], ah0, ah1, ah2, ah3, b.x, b.y);
                    MMA16816(d[nt], ah0, ah1, ah2, ah3, b.z, b.w);
                    MMA16816(d[nt], al0, al1, al2, al3, b.x, b.y);
                }
            }

            int r = row0 + wid * 16 + (lane >> 2);
            int cb = (lane & 3) * 2;
#pragma unroll
            for (int nt = 0; nt < 8; nt++) {
                int c = half * 64 + nt * 8 + cb;
                if (r < NN) {
                    float2 v = make_float2(d[nt][0] + bias[c], d[nt][1] + bias[c + 1]);
                    *(float2*)(dst + r * HC + c) = v;
                }
                if (r + 8 < NN) {
                    float2 v = make_float2(d[nt][2] + bias[c], d[nt][3] + bias[c + 1]);
                    *(float2*)(dst + (r + 8) * HC + c) = v;
                }
            }
        }
    }
}

// ---------------- fused GATv2 layer: LEAN, occupancy-first ---------------------
// 128 thr = 4 warps = 4 nodes/block; regs capped by launch_bounds(128,8).
// per-edge record = single int4 LDG.128.
__global__ void __launch_bounds__(128, 8) gat_layer_kernel(
        const float* __restrict__ We, const float* __restrict__ att,
        const float* __restrict__ bias, int add_res, int write_res) {
    __shared__ float sWe[256];
    __shared__ float sAtt[128];
    int tid = threadIdx.x;
    sWe[tid] = We[tid];
    sWe[tid + 128] = We[tid + 128];
    sAtt[tid] = att[tid];
    __syncthreads();

    int n = blockIdx.x * 4 + (tid >> 5);
    if (n >= NN) return;
    int lane = tid & 31, c0 = lane * 4;
    const unsigned FULL = 0xffffffffu;

    float4 w0 = *(float4*)&sWe[c0];
    float4 w1 = *(float4*)&sWe[128 + c0];
    float4 at = *(float4*)&sAtt[c0];
    float4 xr = *(const float4*)(g_xr + n * HC + c0);
    float4 acc = *(const float4*)(g_xl + n * HC + c0);   // xl_self; becomes accumulator

    float z0 = acc.x + xr.x, z1 = acc.y + xr.y, z2 = acc.z + xr.z, z3 = acc.w + xr.w;
    z0 = z0 > 0.f ? z0 : 0.2f * z0;
    z1 = z1 > 0.f ? z1 : 0.2f * z1;
    z2 = z2 > 0.f ? z2 : 0.2f * z2;
    z3 = z3 > 0.f ? z3 : 0.2f * z3;
    float m = z0 * at.x + z1 * at.y + z2 * at.z + z3 * at.w;
    m += __shfl_xor_sync(FULL, m, 1);
    m += __shfl_xor_sync(FULL, m, 2);
    m += __shfl_xor_sync(FULL, m, 4);
    float s = 1.0f;

    int p = g_rowptr[n], end = g_rowptr[n + 1];

    int4 eA = make_int4(0, 0, 0, 0), eB = eA;
    float4 xlA = make_float4(0.f, 0.f, 0.f, 0.f), xlB = xlA;
    if (p < end) {
        eA = __ldg(&g_cedge[p]);
        xlA = *(const float4*)(g_xl + eA.x * HC + c0);
    }
    if (p + 1 < end) {
        eB = __ldg(&g_cedge[p + 1]);
        xlB = *(const float4*)(g_xl + eB.x * HC + c0);
    }
    for (; p < end; p++) {
        float eax = __int_as_float(eA.z), eay = __int_as_float(eA.w);
        float4 xl = xlA;
        eA = eB; xlA = xlB;
        if (p + 2 < end) {
            eB = __ldg(&g_cedge[p + 2]);
            xlB = *(const float4*)(g_xl + eB.x * HC + c0);
        }

        float y0 = fmaf(eax, w0.x, fmaf(eay, w1.x, xl.x + xr.x));
        float y1 = fmaf(eax, w0.y, fmaf(eay, w1.y, xl.y + xr.y));
        float y2 = fmaf(eax, w0.z, fmaf(eay, w1.z, xl.z + xr.z));
        float y3 = fmaf(eax, w0.w, fmaf(eay, w1.w, xl.w + xr.w));
        y0 = y0 > 0.f ? y0 : 0.2f * y0;
        y1 = y1 > 0.f ? y1 : 0.2f * y1;
        y2 = y2 > 0.f ? y2 : 0.2f * y2;
        y3 = y3 > 0.f ? y3 : 0.2f * y3;
        float q = y0 * at.x + y1 * at.y + y2 * at.z + y3 * at.w;
        q += __shfl_xor_sync(FULL, q, 1);
        q += __shfl_xor_sync(FULL, q, 2);
        q += __shfl_xor_sync(FULL, q, 4);

        float diff = q - m;
        float ex = __expf(-fabsf(diff));
        bool up = diff > 0.f;
        float en = up ? 1.f : ex;
        float eo = up ? ex : 1.f;
        s = fmaf(s, eo, en);
        acc.x = fmaf(acc.x, eo, en * xl.x);
        acc.y = fmaf(acc.y, eo, en * xl.y);
        acc.z = fmaf(acc.z, eo, en * xl.z);
        acc.w = fmaf(acc.w, eo, en * xl.w);
        m = up ? q : m;
    }

    float inv = 1.0f / (s + 1e-16f);
    float4 bv = *(const float4*)(bias + c0);
    float4 o;
    o.x = fmaxf(fmaf(acc.x, inv, bv.x), 0.f);
    o.y = fmaxf(fmaf(acc.y, inv, bv.y), 0.f);
    o.z = fmaxf(fmaf(acc.z, inv, bv.z), 0.f);
    o.w = fmaxf(fmaf(acc.w, inv, bv.w), 0.f);
    if (add_res) {
        float4 r = *(const float4*)(g_res + n * HC + c0);
        o.x += r.x; o.y += r.y; o.z += r.z; o.w += r.w;
    }
    *(float4*)(g_x + n * HC + c0) = o;
    if (write_res) *(float4*)(g_res + n * HC + c0) = o;
}

// ---------------- pooling (zeroing done via cudaMemsetAsync) -------------------
#define POOL_CH 200
__global__ void pool_acc_kernel(const int* __restrict__ batch) {
    int c = threadIdx.x;
    int n0 = blockIdx.x * POOL_CH;
    int n1 = n0 + POOL_CH;
    if (n1 > NN) n1 = NN;
    if (n0 >= NN) return;
    int curb = batch[n0];
    float sm = 0.f, mxv = -INFINITY, cnt = 0.f;
    for (int n = n0; n < n1; n++) {
        int b = batch[n];
        if (b != curb) {
            atomicAdd(&g_mean[curb * HC + c], sm);
            atomicMax(&g_maxenc[curb * HC + c], encf(mxv));
            if (c == 0) atomicAdd(&g_cnt[curb], cnt);
            sm = 0.f; mxv = -INFINITY; cnt = 0.f; curb = b;
        }
        float v = g_x[n * HC + c];
        sm += v;
        mxv = fmaxf(mxv, v);
        cnt += 1.f;
    }
    atomicAdd(&g_mean[curb * HC + c], sm);
    atomicMax(&g_maxenc[curb * HC + c], encf(mxv));
    if (c == 0) atomicAdd(&g_cnt[curb], cnt);
}

__global__ void pool_fin_kernel() {
    int i = blockIdx.x * blockDim.x + threadIdx.x;
    if (i >= NB * HC) return;
    int b = i >> 7, c = i & 127;
    float cnt = g_cnt[b];
    g_X[b * 256 + c] = g_mean[i] / fmaxf(cnt, 1.f);
    g_X[b * 256 + 128 + c] = (cnt > 0.f) ? decf(g_maxenc[i]) : 0.f;
}

// ---------------- dense trunk + heads (one block per graph) -------------------
__global__ void dense_kernel(const float* __restrict__ D1W, const float* __restrict__ D1b,
                             const float* __restrict__ D23W, const float* __restrict__ D23b,
                             const float* __restrict__ H1W, const float* __restrict__ H1b,
                             const float* __restrict__ H2W, const float* __restrict__ H2b,
                             const float* __restrict__ H3W, const float* __restrict__ H3b,
                             float* __restrict__ out) {
    __shared__ float sA[256];
    __shared__ float sB[128];
    __shared__ float sX3[128];
    int b = blockIdx.x, t = threadIdx.x;
    sA[t] = g_X[b * 256 + t];
    sA[t + 128] = g_X[b * 256 + 128 + t];
    __syncthreads();
    float acc = D1b[t];
    for (int k = 0; k < 256; k++) acc = fmaf(sA[k], D1W[k * 128 + t], acc);
    acc = fmaxf(acc, 0.f);
    sB[t] = acc;
    __syncthreads();
    acc = D23b[t];
    for (int k = 0; k < 128; k++) acc = fmaf(sB[k], D23W[k * 128 + t], acc);
    acc = fmaxf(acc, 0.f);
    __syncthreads();
    sA[t] = acc;
    __syncthreads();
    acc = D23b[128 + t];
    for (int k = 0; k < 128; k++) acc = fmaf(sA[k], D23W[16384 + k * 128 + t], acc);
    sX3[t] = fmaxf(acc, 0.f);
    __syncthreads();
    for (int h = 0; h < 3; h++) {
        float a1 = H1b[h * 128 + t];
        for (int k = 0; k < 128; k++) a1 = fmaf(sX3[k], H1W[h * 16384 + k * 128 + t], a1);
        a1 = fmaxf(a1, 0.f);
        sB[t] = a1;
        __syncthreads();
        float a2 = 0.f;
        if (t < 64) {
            a2 = H2b[h * 64 + t];
            for (int k = 0; k < 128; k++) a2 = fmaf(sB[k], H2W[h * 8192 + k * 64 + t], a2);
            a2 = fmaxf(a2, 0.f);
        }
        __syncthreads();
        if (t < 64) sA[t] = a2;
        __syncthreads();
        if (t == 0) {
            float y = H3b[h];
            for (int k = 0; k < 64; k++) y = fmaf(sA[k], H3W[h * 64 + k], y);
            if (h == 0) y = tanhf(y);
            out[b * 3 + h] = y;
        }
        __syncthreads();
    }
}

// ---------------- host ---------------------------------------------------------
extern "C" void kernel_launch(void* const* d_in, const int* in_sizes, int n_in,
                              void* d_out, int out_size) {
    const float* nodes = (const float*)d_in[0];
    const int*   ei    = (const int*)d_in[1];
    const float* ea    = (const float*)d_in[2];
    const int*   batch = (const int*)d_in[3];
    const float* W0l = (const float*)d_in[4];
    const float* b0l = (const float*)d_in[5];
    const float* W0r = (const float*)d_in[6];
    const float* b0r = (const float*)d_in[7];
    const float* W0e = (const float*)d_in[8];
    const float* att0 = (const float*)d_in[9];
    const float* bias0 = (const float*)d_in[10];
    const float* Wl = (const float*)d_in[11];
    const float* bl = (const float*)d_in[12];
    const float* Wr = (const float*)d_in[13];
    const float* br = (const float*)d_in[14];
    const float* We = (const float*)d_in[15];
    const float* atts = (const float*)d_in[16];
    const float* biases = (const float*)d_in[17];
    const float* D1W = (const float*)d_in[18];
    const float* D1b = (const float*)d_in[19];
    const float* D23W = (const float*)d_in[20];
    const float* D23b = (const float*)d_in[21];
    const float* H1W = (const float*)d_in[22];
    const float* H1b = (const float*)d_in[23];
    const float* H2W = (const float*)d_in[24];
    const float* H2b = (const float*)d_in[25];
    const float* H3W = (const float*)d_in[26];
    const float* H3b = (const float*)d_in[27];
    float* out = (float*)d_out;

    cudaFuncSetAttribute(gemm_mma_kernel,
                         cudaFuncAttributeMaxDynamicSharedMemorySize, GSM_TOTAL);

    // zeroing via async memsets (graph memset nodes, not kernel launches)
    void *p_deg, *p_rdy, *p_mean, *p_maxenc, *p_cnt;
    cudaGetSymbolAddress(&p_deg, g_deg);
    cudaGetSymbolAddress(&p_rdy, g_scan_rdy);
    cudaGetSymbolAddress(&p_mean, g_mean);
    cudaGetSymbolAddress(&p_maxenc, g_maxenc);
    cudaGetSymbolAddress(&p_cnt, g_cnt);
    cudaMemsetAsync(p_deg, 0, NN * sizeof(int));
    cudaMemsetAsync(p_rdy, 0, NSB * sizeof(int));
    cudaMemsetAsync(p_mean, 0, NB * HC * sizeof(float));
    cudaMemsetAsync(p_maxenc, 0, NB * HC * sizeof(unsigned));
    cudaMemsetAsync(p_cnt, 0, NB * sizeof(float));

    // k1..k3: CSR build + conv0 linear
    csr_hist_kernel<<<(ER + 255) / 256, 256>>>(ei);
    csr_scan_chain_kernel<<<NSB, SBLK>>>();
    scatter_lin0_kernel<<<(NN * HC + 255) / 256, 256>>>(ei, ea, nodes, W0l, b0l, W0r, b0r);

    // k4: conv0 GAT  <-- profiled launch slot
    gat_layer_kernel<<<(NN + 3) / 4, 128>>>(W0e, att0, bias0, 0, 1);

    // weight fragment prepass for the 8 stacked layers
    wprep_kernel<<<1024, 256>>>(Wl, Wr);

    // 8 stacked convs (4 skip blocks x 2)
    for (int t = 0; t < 8; t++) {
        gemm_mma_kernel<<<NTILES, 256, GSM_TOTAL>>>(t, bl + t * 128, br + t * 128);
        int second = (t & 1);
        gat_layer_kernel<<<(NN + 3) / 4, 128>>>(We + t * 256, atts + t * 128,
                                                biases + t * 128, second, second);
    }

    // pooling
    pool_acc_kernel<<<(NN + POOL_CH - 1) / POOL_CH, 128>>>(batch);
    pool_fin_kernel<<<(NB * HC + 127) / 128, 128>>>();

    // dense trunk + 3 heads
    dense_kernel<<<NB, 128>>>(D1W, D1b, D23W, D23b, H1W, H1b, H2W, H2b, H3W, H3b, out);
}

// round 13
// speedup vs baseline: 1.1225x; 1.1225x over previous
#include <cuda_runtime.h>
#include <cuda_bf16.h>
#include <math.h>
#include <stdint.h>

#define NN 50000
#define ER 600000
#define HC 128
#define NB 50
#define NTILES ((NN + 127) / 128)   // 391
#define SBLK 256
#define NSB ((NN + SBLK - 1) / SBLK)   // 196

// ---------------- scratch (static device globals; no allocation) -------------
__device__ float    g_x[NN * HC];
__device__ float    g_res[NN * HC];
__device__ float    g_xl[NN * HC];
__device__ float    g_xr[NN * HC];
__device__ int      g_deg[NN];
__device__ int      g_rowptr[NN + 1];
__device__ int      g_cur[NN];
__device__ int      g_bsum[NSB];
__device__ int4     g_cedge[ER];         // {src, 0, ea.x bits, ea.y bits}
__device__ float    g_mean[NB * HC];
__device__ unsigned g_maxenc[NB * HC];
__device__ float    g_cnt[NB];
__device__ float    g_X[NB * 256];
__device__ unsigned g_Bfrag[8 * 2 * 8 * 16 * 32 * 4];   // 1 MB

__device__ __forceinline__ unsigned encf(float f) {
    unsigned u = __float_as_uint(f);
    return (u & 0x80000000u) ? ~u : (u | 0x80000000u);
}
__device__ __forceinline__ float decf(unsigned u) {
    return __uint_as_float((u & 0x80000000u) ? (u & 0x7fffffffu) : ~u);
}
__device__ __forceinline__ unsigned pack_hi2(float x, float y) {
    __nv_bfloat16 hx = __float2bfloat16(x), hy = __float2bfloat16(y);
    return (unsigned)__bfloat16_as_ushort(hx) | ((unsigned)__bfloat16_as_ushort(hy) << 16);
}
__device__ __forceinline__ unsigned pack_lo2(float x, float y) {
    __nv_bfloat16 hx = __float2bfloat16(x), hy = __float2bfloat16(y);
    __nv_bfloat16 lx = __float2bfloat16(x - __bfloat162float(hx));
    __nv_bfloat16 ly = __float2bfloat16(y - __bfloat162float(hy));
    return (unsigned)__bfloat16_as_ushort(lx) | ((unsigned)__bfloat16_as_ushort(ly) << 16);
}

#define MMA16816(d, a0, a1, a2, a3, b0, b1) \
    asm volatile("mma.sync.aligned.m16n8k16.row.col.f32.bf16.bf16.f32 " \
        "{%0,%1,%2,%3}, {%4,%5,%6,%7}, {%8,%9}, {%0,%1,%2,%3};" \
        : "+f"((d)[0]), "+f"((d)[1]), "+f"((d)[2]), "+f"((d)[3]) \
        : "r"(a0), "r"(a1), "r"(a2), "r"(a3), "r"(b0), "r"(b1))

// ---------------- CSR build (parallel two-level scan, 2 kernels) ---------------
__global__ void csr_hist_kernel(const int* __restrict__ ei) {
    int e = blockIdx.x * blockDim.x + threadIdx.x;
    if (e < ER) atomicAdd(&g_deg[ei[ER + e]], 1);
}
__global__ void csr_block_sum_kernel() {
    __shared__ int sh[SBLK];
    int b = blockIdx.x, t = threadIdx.x;
    int i = b * SBLK + t;
    sh[t] = (i < NN) ? g_deg[i] : 0;
    __syncthreads();
    for (int o = SBLK / 2; o > 0; o >>= 1) {
        if (t < o) sh[t] += sh[t + o];
        __syncthreads();
    }
    if (t == 0) g_bsum[b] = sh[0];
}
// each block computes its own prefix over the 196 block sums (warp 0 reduce)
__global__ void csr_write_kernel() {
    __shared__ int sh[SBLK];
    __shared__ int bs[NSB];
    __shared__ int prevs;
    int b = blockIdx.x, t = threadIdx.x;
    if (t < NSB) bs[t] = g_bsum[t];
    int i = b * SBLK + t;
    int v = (i < NN) ? g_deg[i] : 0;
    sh[t] = v;
    __syncthreads();
    if (t < 32) {
        int ps = 0;
        for (int j = t; j < b; j += 32) ps += bs[j];
        ps += __shfl_xor_sync(0xffffffffu, ps, 1);
        ps += __shfl_xor_sync(0xffffffffu, ps, 2);
        ps += __shfl_xor_sync(0xffffffffu, ps, 4);
        ps += __shfl_xor_sync(0xffffffffu, ps, 8);
        ps += __shfl_xor_sync(0xffffffffu, ps, 16);
        if (t == 0) prevs = ps;
    }
    for (int o = 1; o < SBLK; o <<= 1) {
        int u = (t >= o) ? sh[t - o] : 0;
        __syncthreads();
        sh[t] += u;
        __syncthreads();
    }
    int excl = prevs + sh[t] - v;
    if (i < NN) {
        g_rowptr[i] = excl;
        g_cur[i] = excl;
        if (i == NN - 1) g_rowptr[NN] = excl + v;
    }
}

// fused: CSR scatter (i < ER) + conv0 dual linear (i < NN*HC)
__global__ void scatter_lin0_kernel(const int* __restrict__ ei, const float* __restrict__ ea,
                                    const float* __restrict__ nodes,
                                    const float* __restrict__ W0l, const float* __restrict__ b0l,
                                    const float* __restrict__ W0r, const float* __restrict__ b0r) {
    int i = blockIdx.x * blockDim.x + threadIdx.x;
    if (i < ER) {
        int s = ei[i], d = ei[ER + i];
        int p = atomicAdd(&g_cur[d], 1);
        int4 rec;
        rec.x = s;
        rec.y = 0;
        rec.z = __float_as_int(ea[2 * i]);
        rec.w = __float_as_int(ea[2 * i + 1]);
        g_cedge[p] = rec;
    }
    if (i < NN * HC) {
        int n = i >> 7, c = i & 127;
        float4 nd = *(const float4*)(nodes + n * 4);
        float l = b0l[c] + nd.x * W0l[c] + nd.y * W0l[128 + c] + nd.z * W0l[256 + c] + nd.w * W0l[384 + c];
        float r = b0r[c] + nd.x * W0r[c] + nd.y * W0r[128 + c] + nd.z * W0r[256 + c] + nd.w * W0r[384 + c];
        g_xl[i] = l;
        g_xr[i] = r;
    }
}

// ---------------- weight prepass: W -> per-lane mma B fragments ----------------
__global__ void wprep_kernel(const float* __restrict__ Wl, const float* __restrict__ Wr) {
    int i = blockIdx.x * blockDim.x + threadIdx.x;
    if (i >= 262144) return;
    int reg = i & 3;
    int lane = (i >> 2) & 31;
    int nt = (i >> 7) & 15;
    int kstep = (i >> 11) & 7;
    int o = (i >> 14) & 1;
    int t = i >> 15;
    const float* W = (o ? Wr : Wl) + t * 16384;
    int n = nt * 8 + (lane >> 2);
    int k = kstep * 16 + (lane & 3) * 2 + ((reg & 1) ? 8 : 0);
    float v0 = W[k * 128 + n];
    float v1 = W[(k + 1) * 128 + n];
    g_Bfrag[i] = (reg < 2) ? pack_hi2(v0, v1) : pack_lo2(v0, v1);
}

// ---------------- mma.sync dual GEMM, B loaded in 32KB n-halves ----------------
#define GSM_ALO 34816
#define GSM_B   69632
#define GSM_TOTAL (69632 + 32768)

__global__ void __launch_bounds__(256, 2) gemm_mma_kernel(
        int layer, const float* __restrict__ bl, const float* __restrict__ br) {
    extern __shared__ __align__(16) char smem[];
    unsigned* Ahi = (unsigned*)smem;
    unsigned* Alo = (unsigned*)(smem + GSM_ALO);
    uint4*    Bs  = (uint4*)(smem + GSM_B);
    int tid = threadIdx.x, wid = tid >> 5, lane = tid & 31;
    int row0 = blockIdx.x * 128;

    for (int j = tid; j < 4096; j += 256) {
        int r = j >> 5, c4 = j & 31;
        int gr = row0 + r;
        float4 v = (gr < NN) ? *(const float4*)(g_x + gr * HC + c4 * 4)
                             : make_float4(0.f, 0.f, 0.f, 0.f);
        int w = r * 68 + c4 * 2;
        Ahi[w]     = pack_hi2(v.x, v.y);
        Ahi[w + 1] = pack_hi2(v.z, v.w);
        Alo[w]     = pack_lo2(v.x, v.y);
        Alo[w + 1] = pack_lo2(v.z, v.w);
    }

    int ab = (wid * 16 + (lane >> 2)) * 68 + (lane & 3);
#pragma unroll
    for (int o = 0; o < 2; o++) {
        const float* bias = o ? br : bl;
        float* dst = o ? g_xr : g_xl;
#pragma unroll
        for (int half = 0; half < 2; half++) {
            __syncthreads();
            {
                const uint4* src = (const uint4*)g_Bfrag + (layer * 2 + o) * 4096;
                for (int j = tid; j < 2048; j += 256) {
                    int chunk = j >> 5;
                    int ks = chunk >> 3, ntl = chunk & 7;
                    Bs[j] = src[(ks * 16 + half * 8 + ntl) * 32 + (j & 31)];
                }
            }
            __syncthreads();

            float d[8][4];
#pragma unroll
            for (int nt = 0; nt < 8; nt++) {
                d[nt][0] = 0.f; d[nt][1] = 0.f; d[nt][2] = 0.f; d[nt][3] = 0.f;
            }
#pragma unroll
            for (int ks = 0; ks < 8; ks++) {
                unsigned ah0 = Ahi[ab + ks * 8];
                unsigned ah1 = Ahi[ab + 8 * 68 + ks * 8];
                unsigned ah2 = Ahi[ab + ks * 8 + 4];
                unsigned ah3 = Ahi[ab + 8 * 68 + ks * 8 + 4];
                unsigned al0 = Alo[ab + ks * 8];
                unsigned al1 = Alo[ab + 8 * 68 + ks * 8];
                unsigned al2 = Alo[ab + ks * 8 + 4];
                unsigned al3 = Alo[ab + 8 * 68 + ks * 8 + 4];
#pragma unroll
                for (int nt = 0; nt < 8; nt++) {
                    uint4 b = Bs[(ks * 8 + nt) * 32 + lane];
                    MMA16816(d[nt], ah0, ah1, ah2, ah3, b.x, b.y);
                    MMA16816(d[nt], ah0, ah1, ah2, ah3, b.z, b.w);
                    MMA16816(d[nt], al0, al1, al2, al3, b.x, b.y);
                }
            }

            int r = row0 + wid * 16 + (lane >> 2);
            int cb = (lane & 3) * 2;
#pragma unroll
            for (int nt = 0; nt < 8; nt++) {
                int c = half * 64 + nt * 8 + cb;
                if (r < NN) {
                    float2 v = make_float2(d[nt][0] + bias[c], d[nt][1] + bias[c + 1]);
                    *(float2*)(dst + r * HC + c) = v;
                }
                if (r + 8 < NN) {
                    float2 v = make_float2(d[nt][2] + bias[c], d[nt][3] + bias[c + 1]);
                    *(float2*)(dst + (r + 8) * HC + c) = v;
                }
            }
        }
    }
}

// ---------------- fused GATv2 layer: lean + pair-merged online softmax ---------
// 128 thr = 4 warps = 4 nodes/block; regs capped by launch_bounds(128,8).
__global__ void __launch_bounds__(128, 8) gat_layer_kernel(
        const float* __restrict__ We, const float* __restrict__ att,
        const float* __restrict__ bias, int add_res, int write_res) {
    __shared__ float sWe[256];
    __shared__ float sAtt[128];
    int tid = threadIdx.x;
    sWe[tid] = We[tid];
    sWe[tid + 128] = We[tid + 128];
    sAtt[tid] = att[tid];
    __syncthreads();

    int n = blockIdx.x * 4 + (tid >> 5);
    if (n >= NN) return;
    int lane = tid & 31, c0 = lane * 4;
    const unsigned FULL = 0xffffffffu;

    float4 w0 = *(float4*)&sWe[c0];
    float4 w1 = *(float4*)&sWe[128 + c0];
    float4 at = *(float4*)&sAtt[c0];
    float4 xr = *(const float4*)(g_xr + n * HC + c0);
    float4 acc = *(const float4*)(g_xl + n * HC + c0);   // xl_self -> accumulator

    float z0 = acc.x + xr.x, z1 = acc.y + xr.y, z2 = acc.z + xr.z, z3 = acc.w + xr.w;
    z0 = z0 > 0.f ? z0 : 0.2f * z0;
    z1 = z1 > 0.f ? z1 : 0.2f * z1;
    z2 = z2 > 0.f ? z2 : 0.2f * z2;
    z3 = z3 > 0.f ? z3 : 0.2f * z3;
    float m = z0 * at.x + z1 * at.y + z2 * at.z + z3 * at.w;
    m += __shfl_xor_sync(FULL, m, 1);
    m += __shfl_xor_sync(FULL, m, 2);
    m += __shfl_xor_sync(FULL, m, 4);
    float s = 1.0f;

    int p = g_rowptr[n], end = g_rowptr[n + 1];

    int4 eA = make_int4(0, 0, 0, 0), eB = eA;
    float4 xlA = make_float4(0.f, 0.f, 0.f, 0.f), xlB = xlA;
    if (p < end) {
        eA = __ldg(&g_cedge[p]);
        xlA = *(const float4*)(g_xl + eA.x * HC + c0);
    }
    if (p + 1 < end) {
        eB = __ldg(&g_cedge[p + 1]);
        xlB = *(const float4*)(g_xl + eB.x * HC + c0);
    }

    while (p + 1 < end) {
        float4 a = xlA, b = xlB;
        float ax0 = __int_as_float(eA.z), ay0 = __int_as_float(eA.w);
        float ax1 = __int_as_float(eB.z), ay1 = __int_as_float(eB.w);
        if (p + 2 < end) {
            eA = __ldg(&g_cedge[p + 2]);
            xlA = *(const float4*)(g_xl + eA.x * HC + c0);
        }
        if (p + 3 < end) {
            eB = __ldg(&g_cedge[p + 3]);
            xlB = *(const float4*)(g_xl + eB.x * HC + c0);
        }
        p += 2;

        float y0 = fmaf(ax0, w0.x, fmaf(ay0, w1.x, a.x + xr.x));
        float y1 = fmaf(ax0, w0.y, fmaf(ay0, w1.y, a.y + xr.y));
        float y2 = fmaf(ax0, w0.z, fmaf(ay0, w1.z, a.z + xr.z));
        float y3 = fmaf(ax0, w0.w, fmaf(ay0, w1.w, a.w + xr.w));
        y0 = y0 > 0.f ? y0 : 0.2f * y0;
        y1 = y1 > 0.f ? y1 : 0.2f * y1;
        y2 = y2 > 0.f ? y2 : 0.2f * y2;
        y3 = y3 > 0.f ? y3 : 0.2f * y3;
        float q0 = y0 * at.x + y1 * at.y + y2 * at.z + y3 * at.w;

        float u0 = fmaf(ax1, w0.x, fmaf(ay1, w1.x, b.x + xr.x));
        float u1 = fmaf(ax1, w0.y, fmaf(ay1, w1.y, b.y + xr.y));
        float u2 = fmaf(ax1, w0.z, fmaf(ay1, w1.z, b.z + xr.z));
        float u3 = fmaf(ax1, w0.w, fmaf(ay1, w1.w, b.w + xr.w));
        u0 = u0 > 0.f ? u0 : 0.2f * u0;
        u1 = u1 > 0.f ? u1 : 0.2f * u1;
        u2 = u2 > 0.f ? u2 : 0.2f * u2;
        u3 = u3 > 0.f ? u3 : 0.2f * u3;
        float q1 = u0 * at.x + u1 * at.y + u2 * at.z + u3 * at.w;

        q0 += __shfl_xor_sync(FULL, q0, 1);
        q1 += __shfl_xor_sync(FULL, q1, 1);
        q0 += __shfl_xor_sync(FULL, q0, 2);
        q1 += __shfl_xor_sync(FULL, q1, 2);
        q0 += __shfl_xor_sync(FULL, q0, 4);
        q1 += __shfl_xor_sync(FULL, q1, 4);

        float mn = fmaxf(m, fmaxf(q0, q1));
        float e0 = __expf(m - mn);
        float e1 = __expf(q0 - mn);
        float e2 = __expf(q1 - mn);
        s = fmaf(s, e0, e1 + e2);
        acc.x = fmaf(acc.x, e0, fmaf(e1, a.x, e2 * b.x));
        acc.y = fmaf(acc.y, e0, fmaf(e1, a.y, e2 * b.y));
        acc.z = fmaf(acc.z, e0, fmaf(e1, a.z, e2 * b.z));
        acc.w = fmaf(acc.w, e0, fmaf(e1, a.w, e2 * b.w));
        m = mn;
    }
    if (p < end) {   // odd tail: remaining edge lives in slot A
        float ax0 = __int_as_float(eA.z), ay0 = __int_as_float(eA.w);
        float y0 = fmaf(ax0, w0.x, fmaf(ay0, w1.x, xlA.x + xr.x));
        float y1 = fmaf(ax0, w0.y, fmaf(ay0, w1.y, xlA.y + xr.y));
        float y2 = fmaf(ax0, w0.z, fmaf(ay0, w1.z, xlA.z + xr.z));
        float y3 = fmaf(ax0, w0.w, fmaf(ay0, w1.w, xlA.w + xr.w));
        y0 = y0 > 0.f ? y0 : 0.2f * y0;
        y1 = y1 > 0.f ? y1 : 0.2f * y1;
        y2 = y2 > 0.f ? y2 : 0.2f * y2;
        y3 = y3 > 0.f ? y3 : 0.2f * y3;
        float q0 = y0 * at.x + y1 * at.y + y2 * at.z + y3 * at.w;
        q0 += __shfl_xor_sync(FULL, q0, 1);
        q0 += __shfl_xor_sync(FULL, q0, 2);
        q0 += __shfl_xor_sync(FULL, q0, 4);
        float mn = fmaxf(m, q0);
        float e0 = __expf(m - mn);
        float e1 = __expf(q0 - mn);
        s = fmaf(s, e0, e1);
        acc.x = fmaf(acc.x, e0, e1 * xlA.x);
        acc.y = fmaf(acc.y, e0, e1 * xlA.y);
        acc.z = fmaf(acc.z, e0, e1 * xlA.z);
        acc.w = fmaf(acc.w, e0, e1 * xlA.w);
        m = mn;
    }

    float inv = 1.0f / (s + 1e-16f);
    float4 bv = *(const float4*)(bias + c0);
    float4 o;
    o.x = fmaxf(fmaf(acc.x, inv, bv.x), 0.f);
    o.y = fmaxf(fmaf(acc.y, inv, bv.y), 0.f);
    o.z = fmaxf(fmaf(acc.z, inv, bv.z), 0.f);
    o.w = fmaxf(fmaf(acc.w, inv, bv.w), 0.f);
    if (add_res) {
        float4 r = *(const float4*)(g_res + n * HC + c0);
        o.x += r.x; o.y += r.y; o.z += r.z; o.w += r.w;
    }
    *(float4*)(g_x + n * HC + c0) = o;
    if (write_res) *(float4*)(g_res + n * HC + c0) = o;
}

// ---------------- pooling (zeroing via cudaMemsetAsync) ------------------------
#define POOL_CH 200
__global__ void pool_acc_kernel(const int* __restrict__ batch) {
    int c = threadIdx.x;
    int n0 = blockIdx.x * POOL_CH;
    int n1 = n0 + POOL_CH;
    if (n1 > NN) n1 = NN;
    if (n0 >= NN) return;
    int curb = batch[n0];
    float sm = 0.f, mxv = -INFINITY, cnt = 0.f;
    for (int n = n0; n < n1; n++) {
        int b = batch[n];
        if (b != curb) {
            atomicAdd(&g_mean[curb * HC + c], sm);
            atomicMax(&g_maxenc[curb * HC + c], encf(mxv));
            if (c == 0) atomicAdd(&g_cnt[curb], cnt);
            sm = 0.f; mxv = -INFINITY; cnt = 0.f; curb = b;
        }
        float v = g_x[n * HC + c];
        sm += v;
        mxv = fmaxf(mxv, v);
        cnt += 1.f;
    }
    atomicAdd(&g_mean[curb * HC + c], sm);
    atomicMax(&g_maxenc[curb * HC + c], encf(mxv));
    if (c == 0) atomicAdd(&g_cnt[curb], cnt);
}

__global__ void pool_fin_kernel() {
    int i = blockIdx.x * blockDim.x + threadIdx.x;
    if (i >= NB * HC) return;
    int b = i >> 7, c = i & 127;
    float cnt = g_cnt[b];
    g_X[b * 256 + c] = g_mean[i] / fmaxf(cnt, 1.f);
    g_X[b * 256 + 128 + c] = (cnt > 0.f) ? decf(g_maxenc[i]) : 0.f;
}

// ---------------- dense trunk + heads (one block per graph) -------------------
__global__ void dense_kernel(const float* __restrict__ D1W, const float* __restrict__ D1b,
                             const float* __restrict__ D23W, const float* __restrict__ D23b,
                             const float* __restrict__ H1W, const float* __restrict__ H1b,
                             const float* __restrict__ H2W, const float* __restrict__ H2b,
                             const float* __restrict__ H3W, const float* __restrict__ H3b,
                             float* __restrict__ out) {
    __shared__ float sA[256];
    __shared__ float sB[128];
    __shared__ float sX3[128];
    int b = blockIdx.x, t = threadIdx.x;
    sA[t] = g_X[b * 256 + t];
    sA[t + 128] = g_X[b * 256 + 128 + t];
    __syncthreads();
    float acc = D1b[t];
    for (int k = 0; k < 256; k++) acc = fmaf(sA[k], D1W[k * 128 + t], acc);
    acc = fmaxf(acc, 0.f);
    sB[t] = acc;
    __syncthreads();
    acc = D23b[t];
    for (int k = 0; k < 128; k++) acc = fmaf(sB[k], D23W[k * 128 + t], acc);
    acc = fmaxf(acc, 0.f);
    __syncthreads();
    sA[t] = acc;
    __syncthreads();
    acc = D23b[128 + t];
    for (int k = 0; k < 128; k++) acc = fmaf(sA[k], D23W[16384 + k * 128 + t], acc);
    sX3[t] = fmaxf(acc, 0.f);
    __syncthreads();
    for (int h = 0; h < 3; h++) {
        float a1 = H1b[h * 128 + t];
        for (int k = 0; k < 128; k++) a1 = fmaf(sX3[k], H1W[h * 16384 + k * 128 + t], a1);
        a1 = fmaxf(a1, 0.f);
        sB[t] = a1;
        __syncthreads();
        float a2 = 0.f;
        if (t < 64) {
            a2 = H2b[h * 64 + t];
            for (int k = 0; k < 128; k++) a2 = fmaf(sB[k], H2W[h * 8192 + k * 64 + t], a2);
            a2 = fmaxf(a2, 0.f);
        }
        __syncthreads();
        if (t < 64) sA[t] = a2;
        __syncthreads();
        if (t == 0) {
            float y = H3b[h];
            for (int k = 0; k < 64; k++) y = fmaf(sA[k], H3W[h * 64 + k], y);
            if (h == 0) y = tanhf(y);
            out[b * 3 + h] = y;
        }
        __syncthreads();
    }
}

// ---------------- host ---------------------------------------------------------
extern "C" void kernel_launch(void* const* d_in, const int* in_sizes, int n_in,
                              void* d_out, int out_size) {
    const float* nodes = (const float*)d_in[0];
    const int*   ei    = (const int*)d_in[1];
    const float* ea    = (const float*)d_in[2];
    const int*   batch = (const int*)d_in[3];
    const float* W0l = (const float*)d_in[4];
    const float* b0l = (const float*)d_in[5];
    const float* W0r = (const float*)d_in[6];
    const float* b0r = (const float*)d_in[7];
    const float* W0e = (const float*)d_in[8];
    const float* att0 = (const float*)d_in[9];
    const float* bias0 = (const float*)d_in[10];
    const float* Wl = (const float*)d_in[11];
    const float* bl = (const float*)d_in[12];
    const float* Wr = (const float*)d_in[13];
    const float* br = (const float*)d_in[14];
    const float* We = (const float*)d_in[15];
    const float* atts = (const float*)d_in[16];
    const float* biases = (const float*)d_in[17];
    const float* D1W = (const float*)d_in[18];
    const float* D1b = (const float*)d_in[19];
    const float* D23W = (const float*)d_in[20];
    const float* D23b = (const float*)d_in[21];
    const float* H1W = (const float*)d_in[22];
    const float* H1b = (const float*)d_in[23];
    const float* H2W = (const float*)d_in[24];
    const float* H2b = (const float*)d_in[25];
    const float* H3W = (const float*)d_in[26];
    const float* H3b = (const float*)d_in[27];
    float* out = (float*)d_out;

    cudaFuncSetAttribute(gemm_mma_kernel,
                         cudaFuncAttributeMaxDynamicSharedMemorySize, GSM_TOTAL);

    // zeroing via async memsets (graph memset nodes, not kernel launches)
    void *p_deg, *p_mean, *p_maxenc, *p_cnt;
    cudaGetSymbolAddress(&p_deg, g_deg);
    cudaGetSymbolAddress(&p_mean, g_mean);
    cudaGetSymbolAddress(&p_maxenc, g_maxenc);
    cudaGetSymbolAddress(&p_cnt, g_cnt);
    cudaMemsetAsync(p_deg, 0, NN * sizeof(int));
    cudaMemsetAsync(p_mean, 0, NB * HC * sizeof(float));
    cudaMemsetAsync(p_maxenc, 0, NB * HC * sizeof(unsigned));
    cudaMemsetAsync(p_cnt, 0, NB * sizeof(float));

    // CSR build (parallel two-level scan) + conv0 linear
    csr_hist_kernel<<<(ER + 255) / 256, 256>>>(ei);
    csr_block_sum_kernel<<<NSB, SBLK>>>();
    csr_write_kernel<<<NSB, SBLK>>>();
    scatter_lin0_kernel<<<(NN * HC + 255) / 256, 256>>>(ei, ea, nodes, W0l, b0l, W0r, b0r);

    // conv0 GAT
    gat_layer_kernel<<<(NN + 3) / 4, 128>>>(W0e, att0, bias0, 0, 1);

    // weight fragment prepass for the 8 stacked layers
    wprep_kernel<<<1024, 256>>>(Wl, Wr);

    // 8 stacked convs (4 skip blocks x 2)
    for (int t = 0; t < 8; t++) {
        gemm_mma_kernel<<<NTILES, 256, GSM_TOTAL>>>(t, bl + t * 128, br + t * 128);
        int second = (t & 1);
        gat_layer_kernel<<<(NN + 3) / 4, 128>>>(We + t * 256, atts + t * 128,
                                                biases + t * 128, second, second);
    }

    // pooling
    pool_acc_kernel<<<(NN + POOL_CH - 1) / POOL_CH, 128>>>(batch);
    pool_fin_kernel<<<(NB * HC + 127) / 128, 128>>>();

    // dense trunk + 3 heads
    dense_kernel<<<NB, 128>>>(D1W, D1b, D23W, D23b, H1W, H1b, H2W, H2b, H3W, H3b, out);
}

// round 15
// speedup vs baseline: 1.1383x; 1.0141x over previous
#include <cuda_runtime.h>
#include <cuda_bf16.h>
#include <math.h>
#include <stdint.h>

#define NN 50000
#define ER 600000
#define HC 128
#define NB 50
#define NTILES ((NN + 127) / 128)   // 391
#define SBLK 256
#define NSB ((NN + SBLK - 1) / SBLK)   // 196

// ---------------- scratch (static device globals; no allocation) -------------
__device__ float    g_x[NN * HC];
__device__ float    g_res[NN * HC];
__device__ float    g_xl[NN * HC];
__device__ float    g_xr[NN * HC];
__device__ int      g_deg[NN];
__device__ int      g_rowptr[NN + 1];
__device__ int      g_cur[NN];
__device__ int      g_bsum[NSB];
__device__ int4     g_cedge[ER];         // {src*512 (byte off), 0, ea.x bits, ea.y bits}
__device__ float    g_mean[NB * HC];
__device__ unsigned g_maxenc[NB * HC];
__device__ float    g_cnt[NB];
__device__ float    g_X[NB * 256];
__device__ unsigned g_Bfrag[8 * 2 * 8 * 16 * 32 * 4];   // 1 MB

__device__ __forceinline__ unsigned encf(float f) {
    unsigned u = __float_as_uint(f);
    return (u & 0x80000000u) ? ~u : (u | 0x80000000u);
}
__device__ __forceinline__ float decf(unsigned u) {
    return __uint_as_float((u & 0x80000000u) ? (u & 0x7fffffffu) : ~u);
}
__device__ __forceinline__ unsigned pack_hi2(float x, float y) {
    __nv_bfloat16 hx = __float2bfloat16(x), hy = __float2bfloat16(y);
    return (unsigned)__bfloat16_as_ushort(hx) | ((unsigned)__bfloat16_as_ushort(hy) << 16);
}
__device__ __forceinline__ unsigned pack_lo2(float x, float y) {
    __nv_bfloat16 hx = __float2bfloat16(x), hy = __float2bfloat16(y);
    __nv_bfloat16 lx = __float2bfloat16(x - __bfloat162float(hx));
    __nv_bfloat16 ly = __float2bfloat16(y - __bfloat162float(hy));
    return (unsigned)__bfloat16_as_ushort(lx) | ((unsigned)__bfloat16_as_ushort(ly) << 16);
}

#define MMA16816(d, a0, a1, a2, a3, b0, b1) \
    asm volatile("mma.sync.aligned.m16n8k16.row.col.f32.bf16.bf16.f32 " \
        "{%0,%1,%2,%3}, {%4,%5,%6,%7}, {%8,%9}, {%0,%1,%2,%3};" \
        : "+f"((d)[0]), "+f"((d)[1]), "+f"((d)[2]), "+f"((d)[3]) \
        : "r"(a0), "r"(a1), "r"(a2), "r"(a3), "r"(b0), "r"(b1))

// ---------------- CSR build (parallel two-level scan) --------------------------
__global__ void csr_hist_kernel(const int* __restrict__ ei) {
    int e = blockIdx.x * blockDim.x + threadIdx.x;
    if (e < ER) atomicAdd(&g_deg[ei[ER + e]], 1);
}
__global__ void csr_block_sum_kernel() {
    __shared__ int sh[SBLK];
    int b = blockIdx.x, t = threadIdx.x;
    int i = b * SBLK + t;
    sh[t] = (i < NN) ? g_deg[i] : 0;
    __syncthreads();
    for (int o = SBLK / 2; o > 0; o >>= 1) {
        if (t < o) sh[t] += sh[t + o];
        __syncthreads();
    }
    if (t == 0) g_bsum[b] = sh[0];
}
__global__ void csr_write_kernel() {
    __shared__ int sh[SBLK];
    __shared__ int bs[NSB];
    __shared__ int prevs;
    int b = blockIdx.x, t = threadIdx.x;
    if (t < NSB) bs[t] = g_bsum[t];
    int i = b * SBLK + t;
    int v = (i < NN) ? g_deg[i] : 0;
    sh[t] = v;
    __syncthreads();
    if (t < 32) {
        int ps = 0;
        for (int j = t; j < b; j += 32) ps += bs[j];
        ps += __shfl_xor_sync(0xffffffffu, ps, 1);
        ps += __shfl_xor_sync(0xffffffffu, ps, 2);
        ps += __shfl_xor_sync(0xffffffffu, ps, 4);
        ps += __shfl_xor_sync(0xffffffffu, ps, 8);
        ps += __shfl_xor_sync(0xffffffffu, ps, 16);
        if (t == 0) prevs = ps;
    }
    for (int o = 1; o < SBLK; o <<= 1) {
        int u = (t >= o) ? sh[t - o] : 0;
        __syncthreads();
        sh[t] += u;
        __syncthreads();
    }
    int excl = prevs + sh[t] - v;
    if (i < NN) {
        g_rowptr[i] = excl;
        g_cur[i] = excl;
        if (i == NN - 1) g_rowptr[NN] = excl + v;
    }
}

// fused: CSR scatter (i < ER) + conv0 dual linear (i < NN*HC)
__global__ void scatter_lin0_kernel(const int* __restrict__ ei, const float* __restrict__ ea,
                                    const float* __restrict__ nodes,
                                    const float* __restrict__ W0l, const float* __restrict__ b0l,
                                    const float* __restrict__ W0r, const float* __restrict__ b0r) {
    int i = blockIdx.x * blockDim.x + threadIdx.x;
    if (i < ER) {
        int s = ei[i], d = ei[ER + i];
        int p = atomicAdd(&g_cur[d], 1);
        int4 rec;
        rec.x = s * (HC * 4);   // byte offset into g_xl
        rec.y = 0;
        rec.z = __float_as_int(ea[2 * i]);
        rec.w = __float_as_int(ea[2 * i + 1]);
        g_cedge[p] = rec;
    }
    if (i < NN * HC) {
        int n = i >> 7, c = i & 127;
        float4 nd = *(const float4*)(nodes + n * 4);
        float l = b0l[c] + nd.x * W0l[c] + nd.y * W0l[128 + c] + nd.z * W0l[256 + c] + nd.w * W0l[384 + c];
        float r = b0r[c] + nd.x * W0r[c] + nd.y * W0r[128 + c] + nd.z * W0r[256 + c] + nd.w * W0r[384 + c];
        g_xl[i] = l;
        g_xr[i] = r;
    }
}

// ---------------- weight prepass: W -> per-lane mma B fragments ----------------
__global__ void wprep_kernel(const float* __restrict__ Wl, const float* __restrict__ Wr) {
    int i = blockIdx.x * blockDim.x + threadIdx.x;
    if (i >= 262144) return;
    int reg = i & 3;
    int lane = (i >> 2) & 31;
    int nt = (i >> 7) & 15;
    int kstep = (i >> 11) & 7;
    int o = (i >> 14) & 1;
    int t = i >> 15;
    const float* W = (o ? Wr : Wl) + t * 16384;
    int n = nt * 8 + (lane >> 2);
    int k = kstep * 16 + (lane & 3) * 2 + ((reg & 1) ? 8 : 0);
    float v0 = W[k * 128 + n];
    float v1 = W[(k + 1) * 128 + n];
    g_Bfrag[i] = (reg < 2) ? pack_hi2(v0, v1) : pack_lo2(v0, v1);
}

// ---------------- mma.sync dual GEMM, B loaded in 32KB n-halves ----------------
#define GSM_ALO 34816
#define GSM_B   69632
#define GSM_TOTAL (69632 + 32768)

__global__ void __launch_bounds__(256, 2) gemm_mma_kernel(
        int layer, const float* __restrict__ bl, const float* __restrict__ br) {
    extern __shared__ __align__(16) char smem[];
    unsigned* Ahi = (unsigned*)smem;
    unsigned* Alo = (unsigned*)(smem + GSM_ALO);
    uint4*    Bs  = (uint4*)(smem + GSM_B);
    int tid = threadIdx.x, wid = tid >> 5, lane = tid & 31;
    int row0 = blockIdx.x * 128;

    for (int j = tid; j < 4096; j += 256) {
        int r = j >> 5, c4 = j & 31;
        int gr = row0 + r;
        float4 v = (gr < NN) ? *(const float4*)(g_x + gr * HC + c4 * 4)
                             : make_float4(0.f, 0.f, 0.f, 0.f);
        int w = r * 68 + c4 * 2;
        Ahi[w]     = pack_hi2(v.x, v.y);
        Ahi[w + 1] = pack_hi2(v.z, v.w);
        Alo[w]     = pack_lo2(v.x, v.y);
        Alo[w + 1] = pack_lo2(v.z, v.w);
    }

    int ab = (wid * 16 + (lane >> 2)) * 68 + (lane & 3);
#pragma unroll
    for (int o = 0; o < 2; o++) {
        const float* bias = o ? br : bl;
        float* dst = o ? g_xr : g_xl;
#pragma unroll
        for (int half = 0; half < 2; half++) {
            __syncthreads();
            {
                const uint4* src = (const uint4*)g_Bfrag + (layer * 2 + o) * 4096;
                for (int j = tid; j < 2048; j += 256) {
                    int chunk = j >> 5;
                    int ks = chunk >> 3, ntl = chunk & 7;
                    Bs[j] = src[(ks * 16 + half * 8 + ntl) * 32 + (j & 31)];
                }
            }
            __syncthreads();

            float d[8][4];
#pragma unroll
            for (int nt = 0; nt < 8; nt++) {
                d[nt][0] = 0.f; d[nt][1] = 0.f; d[nt][2] = 0.f; d[nt][3] = 0.f;
            }
#pragma unroll
            for (int ks = 0; ks < 8; ks++) {
                unsigned ah0 = Ahi[ab + ks * 8];
                unsigned ah1 = Ahi[ab + 8 * 68 + ks * 8];
                unsigned ah2 = Ahi[ab + ks * 8 + 4];
                unsigned ah3 = Ahi[ab + 8 * 68 + ks * 8 + 4];
                unsigned al0 = Alo[ab + ks * 8];
                unsigned al1 = Alo[ab + 8 * 68 + ks * 8];
                unsigned al2 = Alo[ab + ks * 8 + 4];
                unsigned al3 = Alo[ab + 8 * 68 + ks * 8 + 4];
#pragma unroll
                for (int nt = 0; nt < 8; nt++) {
                    uint4 b = Bs[(ks * 8 + nt) * 32 + lane];
                    MMA16816(d[nt], ah0, ah1, ah2, ah3, b.x, b.y);
                    MMA16816(d[nt], ah0, ah1, ah2, ah3, b.z, b.w);
                    MMA16816(d[nt], al0, al1, al2, al3, b.x, b.y);
                }
            }

            int r = row0 + wid * 16 + (lane >> 2);
            int cb = (lane & 3) * 2;
#pragma unroll
            for (int nt = 0; nt < 8; nt++) {
                int c = half * 64 + nt * 8 + cb;
                if (r < NN) {
                    float2 v = make_float2(d[nt][0] + bias[c], d[nt][1] + bias[c + 1]);
                    *(float2*)(dst + r * HC + c) = v;
                }
                if (r + 8 < NN) {
                    float2 v = make_float2(d[nt][2] + bias[c], d[nt][3] + bias[c + 1]);
                    *(float2*)(dst + (r + 8) * HC + c) = v;
                }
            }
        }
    }
}

// ---------------- fused GATv2 layer: lean + pair-merged + byte-offset gathers --
__global__ void __launch_bounds__(128, 8) gat_layer_kernel(
        const float* __restrict__ We, const float* __restrict__ att,
        const float* __restrict__ bias, int add_res, int write_res) {
    __shared__ float sWe[256];
    __shared__ float sAtt[128];
    int tid = threadIdx.x;
    sWe[tid] = We[tid];
    sWe[tid + 128] = We[tid + 128];
    sAtt[tid] = att[tid];
    __syncthreads();

    int n = blockIdx.x * 4 + (tid >> 5);
    if (n >= NN) return;
    int lane = tid & 31, c0 = lane * 4;
    const unsigned FULL = 0xffffffffu;
    const char* xlb = (const char*)g_xl + c0 * 4;   // per-lane byte base

    float4 w0 = *(float4*)&sWe[c0];
    float4 w1 = *(float4*)&sWe[128 + c0];
    float4 at = *(float4*)&sAtt[c0];
    float4 xr = *(const float4*)(g_xr + n * HC + c0);
    float4 acc = *(const float4*)(xlb + n * (HC * 4));   // xl_self -> accumulator

    float z0 = acc.x + xr.x, z1 = acc.y + xr.y, z2 = acc.z + xr.z, z3 = acc.w + xr.w;
    z0 = z0 > 0.f ? z0 : 0.2f * z0;
    z1 = z1 > 0.f ? z1 : 0.2f * z1;
    z2 = z2 > 0.f ? z2 : 0.2f * z2;
    z3 = z3 > 0.f ? z3 : 0.2f * z3;
    float m = z0 * at.x + z1 * at.y + z2 * at.z + z3 * at.w;
    m += __shfl_xor_sync(FULL, m, 1);
    m += __shfl_xor_sync(FULL, m, 2);
    m += __shfl_xor_sync(FULL, m, 4);
    float s = 1.0f;

    int p = g_rowptr[n], end = g_rowptr[n + 1];

    int4 eA = make_int4(0, 0, 0, 0), eB = eA;
    float4 xlA = make_float4(0.f, 0.f, 0.f, 0.f), xlB = xlA;
    if (p < end) {
        eA = __ldg(&g_cedge[p]);
        xlA = *(const float4*)(xlb + eA.x);
    }
    if (p + 1 < end) {
        eB = __ldg(&g_cedge[p + 1]);
        xlB = *(const float4*)(xlb + eB.x);
    }

    while (p + 1 < end) {
        float4 a = xlA, b = xlB;
        float ax0 = __int_as_float(eA.z), ay0 = __int_as_float(eA.w);
        float ax1 = __int_as_float(eB.z), ay1 = __int_as_float(eB.w);
        if (p + 2 < end) {
            eA = __ldg(&g_cedge[p + 2]);
            xlA = *(const float4*)(xlb + eA.x);
        }
        if (p + 3 < end) {
            eB = __ldg(&g_cedge[p + 3]);
            xlB = *(const float4*)(xlb + eB.x);
        }
        p += 2;

        float y0 = fmaf(ax0, w0.x, fmaf(ay0, w1.x, a.x + xr.x));
        float y1 = fmaf(ax0, w0.y, fmaf(ay0, w1.y, a.y + xr.y));
        float y2 = fmaf(ax0, w0.z, fmaf(ay0, w1.z, a.z + xr.z));
        float y3 = fmaf(ax0, w0.w, fmaf(ay0, w1.w, a.w + xr.w));
        y0 = y0 > 0.f ? y0 : 0.2f * y0;
        y1 = y1 > 0.f ? y1 : 0.2f * y1;
        y2 = y2 > 0.f ? y2 : 0.2f * y2;
        y3 = y3 > 0.f ? y3 : 0.2f * y3;
        float q0 = y0 * at.x + y1 * at.y + y2 * at.z + y3 * at.w;

        float u0 = fmaf(ax1, w0.x, fmaf(ay1, w1.x, b.x + xr.x));
        float u1 = fmaf(ax1, w0.y, fmaf(ay1, w1.y, b.y + xr.y));
        float u2 = fmaf(ax1, w0.z, fmaf(ay1, w1.z, b.z + xr.z));
        float u3 = fmaf(ax1, w0.w, fmaf(ay1, w1.w, b.w + xr.w));
        u0 = u0 > 0.f ? u0 : 0.2f * u0;
        u1 = u1 > 0.f ? u1 : 0.2f * u1;
        u2 = u2 > 0.f ? u2 : 0.2f * u2;
        u3 = u3 > 0.f ? u3 : 0.2f * u3;
        float q1 = u0 * at.x + u1 * at.y + u2 * at.z + u3 * at.w;

        q0 += __shfl_xor_sync(FULL, q0, 1);
        q1 += __shfl_xor_sync(FULL, q1, 1);
        q0 += __shfl_xor_sync(FULL, q0, 2);
        q1 += __shfl_xor_sync(FULL, q1, 2);
        q0 += __shfl_xor_sync(FULL, q0, 4);
        q1 += __shfl_xor_sync(FULL, q1, 4);

        float mn = fmaxf(m, fmaxf(q0, q1));
        float e0 = __expf(m - mn);
        float e1 = __expf(q0 - mn);
        float e2 = __expf(q1 - mn);
        s = fmaf(s, e0, e1 + e2);
        acc.x = fmaf(acc.x, e0, fmaf(e1, a.x, e2 * b.x));
        acc.y = fmaf(acc.y, e0, fmaf(e1, a.y, e2 * b.y));
        acc.z = fmaf(acc.z, e0, fmaf(e1, a.z, e2 * b.z));
        acc.w = fmaf(acc.w, e0, fmaf(e1, a.w, e2 * b.w));
        m = mn;
    }
    if (p < end) {   // odd tail: remaining edge in slot A
        float ax0 = __int_as_float(eA.z), ay0 = __int_as_float(eA.w);
        float y0 = fmaf(ax0, w0.x, fmaf(ay0, w1.x, xlA.x + xr.x));
        float y1 = fmaf(ax0, w0.y, fmaf(ay0, w1.y, xlA.y + xr.y));
        float y2 = fmaf(ax0, w0.z, fmaf(ay0, w1.z, xlA.z + xr.z));
        float y3 = fmaf(ax0, w0.w, fmaf(ay0, w1.w, xlA.w + xr.w));
        y0 = y0 > 0.f ? y0 : 0.2f * y0;
        y1 = y1 > 0.f ? y1 : 0.2f * y1;
        y2 = y2 > 0.f ? y2 : 0.2f * y2;
        y3 = y3 > 0.f ? y3 : 0.2f * y3;
        float q0 = y0 * at.x + y1 * at.y + y2 * at.z + y3 * at.w;
        q0 += __shfl_xor_sync(FULL, q0, 1);
        q0 += __shfl_xor_sync(FULL, q0, 2);
        q0 += __shfl_xor_sync(FULL, q0, 4);
        float mn = fmaxf(m, q0);
        float e0 = __expf(m - mn);
        float e1 = __expf(q0 - mn);
        s = fmaf(s, e0, e1);
        acc.x = fmaf(acc.x, e0, e1 * xlA.x);
        acc.y = fmaf(acc.y, e0, e1 * xlA.y);
        acc.z = fmaf(acc.z, e0, e1 * xlA.z);
        acc.w = fmaf(acc.w, e0, e1 * xlA.w);
        m = mn;
    }

    float inv = 1.0f / (s + 1e-16f);
    float4 bv = *(const float4*)(bias + c0);
    float4 o;
    o.x = fmaxf(fmaf(acc.x, inv, bv.x), 0.f);
    o.y = fmaxf(fmaf(acc.y, inv, bv.y), 0.f);
    o.z = fmaxf(fmaf(acc.z, inv, bv.z), 0.f);
    o.w = fmaxf(fmaf(acc.w, inv, bv.w), 0.f);
    if (add_res) {
        float4 r = *(const float4*)(g_res + n * HC + c0);
        o.x += r.x; o.y += r.y; o.z += r.z; o.w += r.w;
    }
    *(float4*)(g_x + n * HC + c0) = o;
    if (write_res) *(float4*)(g_res + n * HC + c0) = o;
}

// ---------------- pooling (zeroing via cudaMemsetAsync) ------------------------
#define POOL_CH 200
__global__ void pool_acc_kernel(const int* __restrict__ batch) {
    int c = threadIdx.x;
    int n0 = blockIdx.x * POOL_CH;
    int n1 = n0 + POOL_CH;
    if (n1 > NN) n1 = NN;
    if (n0 >= NN) return;
    int curb = batch[n0];
    float sm = 0.f, mxv = -INFINITY, cnt = 0.f;
    for (int n = n0; n < n1; n++) {
        int b = batch[n];
        if (b != curb) {
            atomicAdd(&g_mean[curb * HC + c], sm);
            atomicMax(&g_maxenc[curb * HC + c], encf(mxv));
            if (c == 0) atomicAdd(&g_cnt[curb], cnt);
            sm = 0.f; mxv = -INFINITY; cnt = 0.f; curb = b;
        }
        float v = g_x[n * HC + c];
        sm += v;
        mxv = fmaxf(mxv, v);
        cnt += 1.f;
    }
    atomicAdd(&g_mean[curb * HC + c], sm);
    atomicMax(&g_maxenc[curb * HC + c], encf(mxv));
    if (c == 0) atomicAdd(&g_cnt[curb], cnt);
}

__global__ void pool_fin_kernel() {
    int i = blockIdx.x * blockDim.x + threadIdx.x;
    if (i >= NB * HC) return;
    int b = i >> 7, c = i & 127;
    float cnt = g_cnt[b];
    g_X[b * 256 + c] = g_mean[i] / fmaxf(cnt, 1.f);
    g_X[b * 256 + 128 + c] = (cnt > 0.f) ? decf(g_maxenc[i]) : 0.f;
}

// ---------------- dense trunk + heads (one block per graph) -------------------
__global__ void dense_kernel(const float* __restrict__ D1W, const float* __restrict__ D1b,
                             const float* __restrict__ D23W, const float* __restrict__ D23b,
                             const float* __restrict__ H1W, const float* __restrict__ H1b,
                             const float* __restrict__ H2W, const float* __restrict__ H2b,
                             const float* __restrict__ H3W, const float* __restrict__ H3b,
                             float* __restrict__ out) {
    __shared__ float sA[256];
    __shared__ float sB[128];
    __shared__ float sX3[128];
    int b = blockIdx.x, t = threadIdx.x;
    sA[t] = g_X[b * 256 + t];
    sA[t + 128] = g_X[b * 256 + 128 + t];
    __syncthreads();
    float acc = D1b[t];
    for (int k = 0; k < 256; k++) acc = fmaf(sA[k], D1W[k * 128 + t], acc);
    acc = fmaxf(acc, 0.f);
    sB[t] = acc;
    __syncthreads();
    acc = D23b[t];
    for (int k = 0; k < 128; k++) acc = fmaf(sB[k], D23W[k * 128 + t], acc);
    acc = fmaxf(acc, 0.f);
    __syncthreads();
    sA[t] = acc;
    __syncthreads();
    acc = D23b[128 + t];
    for (int k = 0; k < 128; k++) acc = fmaf(sA[k], D23W[16384 + k * 128 + t], acc);
    sX3[t] = fmaxf(acc, 0.f);
    __syncthreads();
    for (int h = 0; h < 3; h++) {
        float a1 = H1b[h * 128 + t];
        for (int k = 0; k < 128; k++) a1 = fmaf(sX3[k], H1W[h * 16384 + k * 128 + t], a1);
        a1 = fmaxf(a1, 0.f);
        sB[t] = a1;
        __syncthreads();
        float a2 = 0.f;
        if (t < 64) {
            a2 = H2b[h * 64 + t];
            for (int k = 0; k < 128; k++) a2 = fmaf(sB[k], H2W[h * 8192 + k * 64 + t], a2);
            a2 = fmaxf(a2, 0.f);
        }
        __syncthreads();
        if (t < 64) sA[t] = a2;
        __syncthreads();
        if (t == 0) {
            float y = H3b[h];
            for (int k = 0; k < 64; k++) y = fmaf(sA[k], H3W[h * 64 + k], y);
            if (h == 0) y = tanhf(y);
            out[b * 3 + h] = y;
        }
        __syncthreads();
    }
}

// ---------------- host ---------------------------------------------------------
extern "C" void kernel_launch(void* const* d_in, const int* in_sizes, int n_in,
                              void* d_out, int out_size) {
    const float* nodes = (const float*)d_in[0];
    const int*   ei    = (const int*)d_in[1];
    const float* ea    = (const float*)d_in[2];
    const int*   batch = (const int*)d_in[3];
    const float* W0l = (const float*)d_in[4];
    const float* b0l = (const float*)d_in[5];
    const float* W0r = (const float*)d_in[6];
    const float* b0r = (const float*)d_in[7];
    const float* W0e = (const float*)d_in[8];
    const float* att0 = (const float*)d_in[9];
    const float* bias0 = (const float*)d_in[10];
    const float* Wl = (const float*)d_in[11];
    const float* bl = (const float*)d_in[12];
    const float* Wr = (const float*)d_in[13];
    const float* br = (const float*)d_in[14];
    const float* We = (const float*)d_in[15];
    const float* atts = (const float*)d_in[16];
    const float* biases = (const float*)d_in[17];
    const float* D1W = (const float*)d_in[18];
    const float* D1b = (const float*)d_in[19];
    const float* D23W = (const float*)d_in[20];
    const float* D23b = (const float*)d_in[21];
    const float* H1W = (const float*)d_in[22];
    const float* H1b = (const float*)d_in[23];
    const float* H2W = (const float*)d_in[24];
    const float* H2b = (const float*)d_in[25];
    const float* H3W = (const float*)d_in[26];
    const float* H3b = (const float*)d_in[27];
    float* out = (float*)d_out;

    cudaFuncSetAttribute(gemm_mma_kernel,
                         cudaFuncAttributeMaxDynamicSharedMemorySize, GSM_TOTAL);

    // zeroing via async memsets (graph memset nodes, not kernel launches)
    void *p_deg, *p_mean, *p_maxenc, *p_cnt;
    cudaGetSymbolAddress(&p_deg, g_deg);
    cudaGetSymbolAddress(&p_mean, g_mean);
    cudaGetSymbolAddress(&p_maxenc, g_maxenc);
    cudaGetSymbolAddress(&p_cnt, g_cnt);
    cudaMemsetAsync(p_deg, 0, NN * sizeof(int));
    cudaMemsetAsync(p_mean, 0, NB * HC * sizeof(float));
    cudaMemsetAsync(p_maxenc, 0, NB * HC * sizeof(unsigned));
    cudaMemsetAsync(p_cnt, 0, NB * sizeof(float));

    // CSR build (parallel two-level scan) + conv0 linear
    csr_hist_kernel<<<(ER + 255) / 256, 256>>>(ei);
    csr_block_sum_kernel<<<NSB, SBLK>>>();
    csr_write_kernel<<<NSB, SBLK>>>();
    scatter_lin0_kernel<<<(NN * HC + 255) / 256, 256>>>(ei, ea, nodes, W0l, b0l, W0r, b0r);

    // conv0 GAT
    gat_layer_kernel<<<(NN + 3) / 4, 128>>>(W0e, att0, bias0, 0, 1);

    // weight fragment prepass for the 8 stacked layers
    wprep_kernel<<<1024, 256>>>(Wl, Wr);

    // 8 stacked convs (4 skip blocks x 2)
    for (int t = 0; t < 8; t++) {
        gemm_mma_kernel<<<NTILES, 256, GSM_TOTAL>>>(t, bl + t * 128, br + t * 128);
        int second = (t & 1);
        gat_layer_kernel<<<(NN + 3) / 4, 128>>>(We + t * 256, atts + t * 128,
                                                biases + t * 128, second, second);
    }

    // pooling
    pool_acc_kernel<<<(NN + POOL_CH - 1) / POOL_CH, 128>>>(batch);
    pool_fin_kernel<<<(NB * HC + 127) / 128, 128>>>();

    // dense trunk + 3 heads
    dense_kernel<<<NB, 128>>>(D1W, D1b, D23W, D23b, H1W, H1b, H2W, H2b, H3W, H3b, out);
}